// round 10
// baseline (speedup 1.0000x reference)
#include <cuda_runtime.h>
#include <cuda_bf16.h>
#include <cstdint>

// AbsolutePositionEncoding: out[b][s][e] = E[s/8][e], b<64, s<2048, e<256 (fp32)
// Pure broadcast-write: 128 MiB stores.
//
// R9: hybrid STG + TMA experiment. R6 (pure STG) and R8 (pure TMA) both hit
// exactly ~6.25 TB/s into L2 (~21.5 us) — evidence of a write-ingest cap at
// the LTS. This kernel drives BOTH paths concurrently, each carrying half the
// batches. If the caps are per-path, time halves; if shared, time is flat and
// 6.25 TB/s is the machine's write ceiling for this pattern.

__global__ __launch_bounds__(256, 8)
void ape_hybrid_kernel(const float4* __restrict__ E4, float4* __restrict__ out4) {
    __shared__ alignas(128) float4 buf[512];   // 8 KB: 8 tokens x 64 f4

    const int obj = blockIdx.x;                // 0..255
    const int t   = threadIdx.x;               // 0..255
    const int b0  = blockIdx.y * 16;           // starting batch: 0,16,32,48

    // One float4 of the row per thread (lane repeats mod 64).
    const float4 v = E4[obj * 64 + (t & 63)];
    buf[t]       = v;
    buf[t + 256] = v;

    __syncthreads();
    asm volatile("fence.proxy.async.shared::cta;" ::: "memory");

    // --- TMA half: batches b0+8 .. b0+15, fire-and-forget ---
    if (t == 0) {
        uint32_t saddr = (uint32_t)__cvta_generic_to_shared(buf);
        const char* gbase = (const char*)out4
                          + (size_t)(b0 + 8) * 2097152ull   // batch stride 2 MiB
                          + (size_t)obj * 8192ull;          // object span 8 KiB
        #pragma unroll
        for (int b = 0; b < 8; ++b) {
            uint64_t g = (uint64_t)(gbase + (size_t)b * 2097152ull);
            asm volatile(
                "cp.async.bulk.global.shared::cta.bulk_group [%0], [%1], %2;"
                :: "l"(g), "r"(saddr), "r"(8192) : "memory");
        }
        asm volatile("cp.async.bulk.commit_group;" ::: "memory");
    }

    // --- STG half: batches b0 .. b0+7, all threads, overlapping the TMA ---
    float4* base = out4 + (size_t)b0 * 131072 + obj * 512 + t;
    #pragma unroll
    for (int b = 0; b < 8; ++b) {
        float4* p = base + (size_t)b * 131072;
        p[0]   = v;   // j = t
        p[256] = v;   // j = t + 256
    }

    // Drain bulk stores before CTA retires (SMEM is the source).
    if (t == 0)
        asm volatile("cp.async.bulk.wait_group 0;" ::: "memory");
}

extern "C" void kernel_launch(void* const* d_in, const int* in_sizes, int n_in,
                              void* d_out, int out_size) {
    // d_in[0] = x (unused), d_in[1] = E_absolute_position [512, 256] fp32
    const float4* E4 = (const float4*)d_in[1];
    float4* out4 = (float4*)d_out;
    dim3 grid(256, 4);
    ape_hybrid_kernel<<<grid, 256>>>(E4, out4);
}

// round 11
// speedup vs baseline: 1.0102x; 1.0102x over previous
#include <cuda_runtime.h>
#include <cuda_bf16.h>

// AbsolutePositionEncoding: out[b][s][e] = E[s/8][e], b<64, s<2048, e<256 (fp32)
// Only objects 0..255 referenced. Pure broadcast-write: 128 MiB stores.
//
// R10: R6 structure (pure STG, best bench so far) + streaming store hint.
// Evidence: STG-only, TMA-only, and hybrid all converge at ~6.3 TB/s write
// ingest (~21.3 us kernel) => shared ceiling ~= HBM write bandwidth
// (8 TB/s spec * ~0.8 write/ECC efficiency). In the timed steady state every
// iteration must evict the prior iteration's dirty L2 lines; st.global.cs
// (evict-first) makes output lines cheap victims with eager writeback,
// smoothing the evict-ingest pipeline. If flat, we are at the roofline.

__global__ __launch_bounds__(256, 8)
void ape_broadcast_cs_kernel(const float4* __restrict__ E4, float4* __restrict__ out4) {
    const int obj = blockIdx.x;              // 0..255
    const int t   = threadIdx.x;             // 0..255
    const int b0  = blockIdx.y * 16;         // starting batch: 0,16,32,48

    // Row of E for this object: 256 floats = 64 float4. Lane repeats mod 64
    // (t and t+256 congruent mod 64 -> one register serves both positions).
    const float4 v = E4[obj * 64 + (t & 63)];

    // Per-batch stride = 2048*256/4 = 131072 f4. Object span within a batch:
    // obj*512 f4, length 512 f4 (256 objs * 512 = 131072 = full batch slice).
    float4* base = out4 + (size_t)b0 * 131072 + obj * 512 + t;

    #pragma unroll
    for (int b = 0; b < 16; ++b) {
        float4* p = base + (size_t)b * 131072;
        __stcs(p,       v);   // j = t       (streaming / evict-first)
        __stcs(p + 256, v);   // j = t + 256
    }
}

extern "C" void kernel_launch(void* const* d_in, const int* in_sizes, int n_in,
                              void* d_out, int out_size) {
    // d_in[0] = x (unused), d_in[1] = E_absolute_position [512, 256] fp32
    const float4* E4 = (const float4*)d_in[1];
    float4* out4 = (float4*)d_out;
    dim3 grid(256, 4);
    ape_broadcast_cs_kernel<<<grid, 256>>>(E4, out4);
}

// round 14
// speedup vs baseline: 1.0115x; 1.0013x over previous
#include <cuda_runtime.h>
#include <cuda_bf16.h>

// AbsolutePositionEncoding: out[b][s][e] = E[s/8][e], b<64, s<2048, e<256 (fp32)
// Only objects 0..255 referenced (2048/8). Pure broadcast-write: 128 MiB stores.
//
// FINAL (resubmit of R11, which passed at 25.088 us; R12 was a container infra
// failure). Measured roofline: the L2 write-ingest port (184 LTS slices x
// 32 B sector/cycle ~= 5.9 kB/cyc ~= 6.3 TB/s) caps every store path
// identically — pure STG (occ 30/50%), TMA bulk (occ 13%), hybrid, and
// streaming-hint variants all land at 21.2-21.6 us kernel time. 134 MB of
// mandatory output / 6.3 TB/s ~= 21.2 us = hardware floor; this kernel sits
// on it with the simplest mechanism.
//
// Grid (256, 4): blockIdx.x = object, blockIdx.y = quarter of the batch dim.
// Thread t holds ONE float4 of the object's row in a register (lane = t & 63;
// t and t+256 are congruent mod 64) and issues 32 warp-contiguous STG.E.128
// (512 B full-line bursts; no read-for-ownership, every line written once).

__global__ __launch_bounds__(256, 8)
void ape_broadcast_kernel(const float4* __restrict__ E4, float4* __restrict__ out4) {
    const int obj = blockIdx.x;              // 0..255
    const int t   = threadIdx.x;             // 0..255
    const int b0  = blockIdx.y * 16;         // starting batch: 0,16,32,48

    // Row of E for this object: 256 floats = 64 float4. Lane repeats mod 64.
    const float4 v = E4[obj * 64 + (t & 63)];

    // Per-batch stride = 2048*256/4 = 131072 f4. Object span within a batch:
    // obj*512 f4, length 512 f4 (256 objs * 512 = 131072 = full batch slice).
    float4* base = out4 + (size_t)b0 * 131072 + obj * 512 + t;

    #pragma unroll
    for (int b = 0; b < 16; ++b) {
        float4* p = base + (size_t)b * 131072;
        p[0]   = v;   // j = t
        p[256] = v;   // j = t + 256
    }
}

extern "C" void kernel_launch(void* const* d_in, const int* in_sizes, int n_in,
                              void* d_out, int out_size) {
    // d_in[0] = x (unused), d_in[1] = E_absolute_position [512, 256] fp32
    const float4* E4 = (const float4*)d_in[1];
    float4* out4 = (float4*)d_out;
    dim3 grid(256, 4);
    ape_broadcast_kernel<<<grid, 256>>>(E4, out4);
}